// round 17
// baseline (speedup 1.0000x reference)
#include <cuda_runtime.h>
#include <cstdint>

#define Bq 8
#define Hq 128
#define Wq 128
#define Cq 128
#define Fq 128

// ---------------------------------------------------------------------------
// Weight slabs, vector-load layout (as R16):
// slab per (b,tap,cc): 128 f-rows, row stride 36 words (32 data + 4 pad),
// within-row k' = (k%4)*8 + k/4.  Values pre-rounded to tf32 (cvt.rna).
// ---------------------------------------------------------------------------
#define WSLAB 4608                     // words per slab: 128 * 36
__device__ float g_wmod[(size_t)Bq * 9 * 4 * WSLAB];
__device__ float g_rr[Bq * Fq];        // demod factors

// ---------------------------------------------------------------------------
// Kernel 1: demodulation factors r[b][f].  grid = Bq, 256 threads.
// ---------------------------------------------------------------------------
__global__ __launch_bounds__(256) void demod_kernel(const float* __restrict__ style,
                                                    const float* __restrict__ kern)
{
    const int b   = blockIdx.x;
    const int tid = threadIdx.x;
    const int f   = tid & 127;
    const int hf  = tid >> 7;          // 0/1 : c half

    __shared__ float ssty[Cq];
    __shared__ float sred[2][Fq];

    if (tid < Cq) ssty[tid] = style[b * Cq + tid] + 1.0f;
    __syncthreads();

    float sq = 0.0f;
    for (int k = 0; k < 9; k++) {
#pragma unroll 4
        for (int j = 0; j < 64; j++) {
            int c = hf * 64 + j;
            float kv = kern[(k * Cq + c) * Fq + f] * ssty[c];
            sq += kv * kv;
        }
    }
    sred[hf][f] = sq;
    __syncthreads();
    if (tid < Fq) {
        float xarg = sred[0][tid] + sred[1][tid] + 1e-8f;
        float r = rsqrtf(xarg);
        r = r * (1.5f - 0.5f * xarg * r * r);   // Newton -> fp32 accuracy
        g_rr[b * Fq + tid] = r;
    }
}

// ---------------------------------------------------------------------------
// Kernel 2: build one 18KB weight slab per CTA.  grid = (36, Bq), 256 threads.
// Stage in smem (scattered perm writes), then linear coalesced store.
// ---------------------------------------------------------------------------
__global__ __launch_bounds__(256) void wslab_kernel(const float* __restrict__ style,
                                                    const float* __restrict__ kern)
{
    const int s   = blockIdx.x;        // 0..35
    const int b   = blockIdx.y;
    const int tap = s >> 2;
    const int cc  = s & 3;
    const int tid = threadIdx.x;

    __shared__ float ssty[32];         // this slab's 32 c values of style+1
    __shared__ float srr[Fq];
    __shared__ float slab[WSLAB];

    if (tid < 32)  ssty[tid] = style[b * Cq + cc * 32 + tid] + 1.0f;
    if (tid < Fq)  srr[tid]  = g_rr[b * Fq + tid];
    // zero pad words (f*36 + 32..35)
    for (int i = tid; i < Fq * 4; i += 256)
        slab[(i >> 2) * 36 + 32 + (i & 3)] = 0.0f;
    __syncthreads();

    for (int i = tid; i < 32 * Fq; i += 256) {
        int cl = i >> 7;               // c_local 0..31
        int f  = i & 127;
        float v = kern[(tap * Cq + cc * 32 + cl) * Fq + f] * ssty[cl] * srr[f];
        uint32_t bits;
        asm("cvt.rna.tf32.f32 %0, %1;" : "=r"(bits) : "f"(v));
        int kp = (cl & 3) * 8 + (cl >> 2);
        slab[f * 36 + kp] = __uint_as_float(bits);
    }
    __syncthreads();

    float4* dst = (float4*)(g_wmod + ((size_t)(b * 9 + tap) * 4 + cc) * WSLAB);
    const float4* src = (const float4*)slab;
    for (int i = tid; i < WSLAB / 4; i += 256)
        dst[i] = src[i];
}

// ---------------------------------------------------------------------------
// Conv kernel: CTA = (b, output row h0). GEMM M=128(w) x N=128(f), K=1152.
// mma.sync.m16n8k8 tf32.  8 warps = 4(m) x 2(n), warp tile 32x64.
// A: scalar LDS from XOR-swizzled band.  B: two LDS.128 per f-row (k-perm slab).
// Band single-buffered, ws triple-buffered. 105216 B smem -> 2 CTAs/SM.
// ---------------------------------------------------------------------------
#define XS_WORDS 12480                 // 3 rows * 130 pos * 32 c floats
#define WS_WORDS WSLAB                 // 4608
#define SMEM_WORDS (XS_WORDS + 3 * WS_WORDS)
#define SMEM_BYTES (SMEM_WORDS * 4)    // 105216

#define NTHREADS 256

__device__ __forceinline__ void cp_async16(uint32_t daddr, const void* saddr, int srcsz) {
    asm volatile("cp.async.cg.shared.global [%0], [%1], 16, %2;"
                 :: "r"(daddr), "l"(saddr), "r"(srcsz) : "memory");
}
__device__ __forceinline__ void cp_commit() {
    asm volatile("cp.async.commit_group;" ::: "memory");
}
__device__ __forceinline__ void cp_wait0() {
    asm volatile("cp.async.wait_group 0;" ::: "memory");
}
__device__ __forceinline__ void cp_wait1() {
    asm volatile("cp.async.wait_group 1;" ::: "memory");
}

__device__ __forceinline__ void mma_tf32(float& c0, float& c1, float& c2, float& c3,
                                         uint32_t a0, uint32_t a1, uint32_t a2, uint32_t a3,
                                         uint32_t b0, uint32_t b1) {
    asm volatile("mma.sync.aligned.m16n8k8.row.col.f32.tf32.tf32.f32 "
                 "{%0,%1,%2,%3}, {%4,%5,%6,%7}, {%8,%9}, {%0,%1,%2,%3};"
                 : "+f"(c0), "+f"(c1), "+f"(c2), "+f"(c3)
                 : "r"(a0), "r"(a1), "r"(a2), "r"(a3), "r"(b0), "r"(b1));
}

__global__ __launch_bounds__(NTHREADS, 2) void conv_tc_kernel(const float* __restrict__ x,
                                                              float* __restrict__ out)
{
    extern __shared__ float sm[];
    uint32_t smbase;
    asm("{ .reg .u64 t; cvta.to.shared.u64 t, %1; cvt.u32.u64 %0, t; }"
        : "=r"(smbase) : "l"(sm));

    const int tid = threadIdx.x;
    const int lane = tid & 31;
    const int wid  = tid >> 5;
    const int g    = lane >> 2;       // groupID (0..7)
    const int tig  = lane & 3;        // thread-in-group
    const int warpM = wid & 3;        // 0..3 (m tiles of 32)
    const int warpN = wid >> 2;       // 0..1 (n tiles of 64)

    const int h0 = blockIdx.x;
    const int b  = blockIdx.y;

    float acc[2][8][4];
#pragma unroll
    for (int mt = 0; mt < 2; mt++)
#pragma unroll
        for (int nt = 0; nt < 8; nt++)
#pragma unroll
            for (int q = 0; q < 4; q++) acc[mt][nt][q] = 0.0f;

    // x band for c-chunk cc (single buffer): xs[r][p][kk], word swizzle kk ^ ((p&7)*4)
    auto fill_band = [&](int cc) {
        const float* xb = x + ((size_t)b * Hq) * Wq * Cq + cc * 32;
        for (int i = tid; i < 3 * 130 * 8; i += NTHREADS) {
            int r   = i / 1040;
            int rem = i - r * 1040;
            int p   = rem >> 3;
            int kk4 = rem & 7;
            int gh = h0 - 1 + r;
            int gw = p - 1;
            int valid = (gh >= 0 && gh < Hq && gw >= 0 && gw < Wq) ? 16 : 0;
            int ghc = gh < 0 ? 0 : (gh > Hq - 1 ? Hq - 1 : gh);
            int gwc = gw < 0 ? 0 : (gw > Wq - 1 ? Wq - 1 : gw);
            const float* src = xb + ((size_t)ghc * Wq + gwc) * Cq + kk4 * 4;
            uint32_t w = (r * 130 + p) * 32 + ((kk4 * 4) ^ ((p & 7) * 4));
            cp_async16(smbase + w * 4, src, valid);
        }
    };
    // weight slab (b,tap,cc) -> ws buffer bb: straight linear 18KB copy
    auto fill_ws = [&](int tap, int cc, int bb) {
        const float* src0 = g_wmod + ((size_t)(b * 9 + tap) * 4 + cc) * WSLAB;
        for (int i = tid; i < WSLAB / 4; i += NTHREADS) {
            uint32_t w = XS_WORDS + bb * WS_WORDS + i * 4;
            cp_async16(smbase + w * 4, src0 + i * 4, 16);
        }
    };

    // ---- prologue ----
    fill_band(0);
    fill_ws(0, 0, 0);
    cp_commit();

    for (int it = 0; it < 36; it++) {
        const int cc  = it / 9;
        const int tap = it - cc * 9;
        const int kh = tap / 3;
        const int kw = tap - kh * 3;

        cp_wait0();                 // data for iter it arrived
        __syncthreads();            // all warps done reading iter it-1 buffers

        if (tap == 0 && cc > 0) {
            fill_band(cc);
            cp_commit();            // group: band (needed THIS iter)
            if (it + 1 < 36) fill_ws((it + 1) % 9, (it + 1) / 9, (it + 1) % 3);
            cp_commit();            // group: next ws (needed next iter)
            cp_wait1();             // wait band only; ws stays in flight
            __syncthreads();
        } else {
            if (it + 1 < 36) fill_ws((it + 1) % 9, (it + 1) / 9, (it + 1) % 3);
            cp_commit();
        }

        const int xb = kh * 130 * 32;
        const int wb = XS_WORDS + (it % 3) * WS_WORDS;

        const int mA = warpM * 32 + g;
        const int pA0 = mA + kw,  pA1 = pA0 + 8;
        const int pB0 = pA0 + 16, pB1 = pA0 + 24;
        const int baseA0 = xb + pA0 * 32, mkA0 = (pA0 & 7) * 4;
        const int baseA1 = xb + pA1 * 32, mkA1 = (pA1 & 7) * 4;
        const int baseB0 = xb + pB0 * 32, mkB0 = (pB0 & 7) * 4;
        const int baseB1 = xb + pB1 * 32, mkB1 = (pB1 & 7) * 4;

        // ---- preload ALL A fragments for the 4 k-steps (32 regs) ----
        uint32_t A0[4][4], A1[4][4];
#pragma unroll
        for (int ks = 0; ks < 4; ks++) {
            const int k0 = ks * 8 + tig;
            A0[ks][0] = __float_as_uint(sm[baseA0 + (k0 ^ mkA0)]);
            A0[ks][2] = __float_as_uint(sm[baseA0 + ((k0 + 4) ^ mkA0)]);
            A0[ks][1] = __float_as_uint(sm[baseA1 + (k0 ^ mkA1)]);
            A0[ks][3] = __float_as_uint(sm[baseA1 + ((k0 + 4) ^ mkA1)]);
            A1[ks][0] = __float_as_uint(sm[baseB0 + (k0 ^ mkB0)]);
            A1[ks][2] = __float_as_uint(sm[baseB0 + ((k0 + 4) ^ mkB0)]);
            A1[ks][1] = __float_as_uint(sm[baseB1 + (k0 ^ mkB1)]);
            A1[ks][3] = __float_as_uint(sm[baseB1 + ((k0 + 4) ^ mkB1)]);
        }

        // ---- B: per f-row, two LDS.128 cover all 4 k-steps ----
        const int fbase = wb + (warpN * 64 + g) * 36 + tig * 8;
#pragma unroll
        for (int nt = 0; nt < 8; nt++) {
            const int frow = fbase + nt * 8 * 36;
            float4 w0 = *(const float4*)&sm[frow];
            float4 w1 = *(const float4*)&sm[frow + 4];
            uint32_t bw[8];
            bw[0] = __float_as_uint(w0.x); bw[1] = __float_as_uint(w0.y);
            bw[2] = __float_as_uint(w0.z); bw[3] = __float_as_uint(w0.w);
            bw[4] = __float_as_uint(w1.x); bw[5] = __float_as_uint(w1.y);
            bw[6] = __float_as_uint(w1.z); bw[7] = __float_as_uint(w1.w);
#pragma unroll
            for (int ks = 0; ks < 4; ks++) {
                mma_tf32(acc[0][nt][0], acc[0][nt][1], acc[0][nt][2], acc[0][nt][3],
                         A0[ks][0], A0[ks][1], A0[ks][2], A0[ks][3],
                         bw[2 * ks], bw[2 * ks + 1]);
                mma_tf32(acc[1][nt][0], acc[1][nt][1], acc[1][nt][2], acc[1][nt][3],
                         A1[ks][0], A1[ks][1], A1[ks][2], A1[ks][3],
                         bw[2 * ks], bw[2 * ks + 1]);
            }
        }
    }

    // ---- epilogue: direct STG from accumulators ----
    float* ob = out + (((size_t)b * Hq + h0) * Wq) * Fq;
#pragma unroll
    for (int mt = 0; mt < 2; mt++) {
        const int m = warpM * 32 + mt * 16 + g;
#pragma unroll
        for (int nt = 0; nt < 8; nt++) {
            const int f = warpN * 64 + nt * 8 + tig * 2;
            float2 v0 = make_float2(acc[mt][nt][0], acc[mt][nt][1]);
            float2 v1 = make_float2(acc[mt][nt][2], acc[mt][nt][3]);
            *(float2*)(ob + (size_t)m * Fq + f) = v0;
            *(float2*)(ob + (size_t)(m + 8) * Fq + f) = v1;
        }
    }
}

// ---------------------------------------------------------------------------
extern "C" void kernel_launch(void* const* d_in, const int* in_sizes, int n_in,
                              void* d_out, int out_size)
{
    const float* x     = (const float*)d_in[0];   // (8,128,128,128) NHWC
    const float* style = (const float*)d_in[1];   // (8,128)
    const float* kern  = (const float*)d_in[2];   // (3,3,128,128)
    float* out = (float*)d_out;

    (void)in_sizes; (void)n_in; (void)out_size;

    cudaFuncSetAttribute(conv_tc_kernel, cudaFuncAttributeMaxDynamicSharedMemorySize, SMEM_BYTES);

    demod_kernel<<<Bq, 256>>>(style, kern);

    dim3 gridW(36, Bq);                            // 288 CTAs, one slab each
    wslab_kernel<<<gridW, 256>>>(style, kern);

    dim3 gridC(Hq, Bq);                            // 128 rows x 8 batch = 1024 CTAs
    conv_tc_kernel<<<gridC, NTHREADS, SMEM_BYTES>>>(x, out);
}